// round 8
// baseline (speedup 1.0000x reference)
#include <cuda_runtime.h>

#define E 8
#define DDIM 1024
#define TPB 128
#define NW 4                       // warps per block
#define GRID 148
#define CFLOAT 32                  // d's per chunk
#define CSLOT (CFLOAT / 4)         // 8 float4 slots per row per chunk
#define NCH (DDIM / CFLOAT)        // 32 chunks
#define STG 3                      // warp-private pipeline stages
#define ROWS_W 64                  // tokens staged per warp (2 per lane)
#define WBUF (ROWS_W * CFLOAT)     // 2048 floats = 8KB per stage per warp
#define SMEM_FLOATS (2 * E * DDIM + NW * STG * WBUF)   // 64KB Wdup + 96KB x
#define SMEM_BYTES (SMEM_FLOATS * 4)                   // 160KB

// Global accumulators. Zero-initialized at module load; the LAST block resets
// them after consuming, so every launch / graph replay sees zeros on entry.
__device__ float g_prob_sum[E];
__device__ float g_ent_sum;
__device__ unsigned g_cnt[E];
__device__ unsigned g_done;

__device__ __forceinline__ void fma2(unsigned long long& acc,
                                     unsigned long long a, unsigned long long b) {
    asm("fma.rn.f32x2 %0, %1, %2, %0;" : "+l"(acc) : "l"(a), "l"(b));
}
__device__ __forceinline__ unsigned long long pack2(float lo, float hi) {
    unsigned long long r;
    asm("mov.b64 %0, {%1, %2};" : "=l"(r) : "f"(lo), "f"(hi));
    return r;
}

// Warp-private chunk stage: 64 token rows x 32 floats, coalesced, swizzled by
// (row>>1)&7 so the pair-reader (lane q reads rows 2q,2q+1) is conflict-free.
__device__ __forceinline__ void warp_issue(const float* __restrict__ x, float* wbuf,
                                           int tok0w, int c, int lane, int N) {
    float* buf = wbuf + (c % STG) * WBUF;
#pragma unroll
    for (int k = 0; k < 16; ++k) {
        int i = lane + k * 32;
        int row = i >> 3;                       // 0..63
        int slot = i & 7;                       // float4 slot
        int gt = tok0w + row; if (gt > N - 1) gt = N - 1;
        const float* src = x + (size_t)gt * DDIM + c * CFLOAT + slot * 4;
        float* dst = buf + row * CFLOAT + ((slot ^ ((row >> 1) & 7)) << 2);
        unsigned d = (unsigned)__cvta_generic_to_shared(dst);
        asm volatile("cp.async.cg.shared.global [%0], [%1], 16;\n" :: "r"(d), "l"(src));
    }
    asm volatile("cp.async.commit_group;\n");
}

__global__ __launch_bounds__(TPB, 1)
void router_main(const float* __restrict__ x, const float* __restrict__ Wg,
                 const int* __restrict__ pk, float* __restrict__ out,
                 int N, int tok_per_blk) {
    extern __shared__ float smem[];
    float* sW2 = smem;                           // duplicated W: float2 (w,w) x E*DDIM
    float* sx  = smem + 2 * E * DDIM;            // [NW][STG][64][CFLOAT]
    __shared__ float sh_psum[E];
    __shared__ unsigned sh_cnt[E];
    __shared__ float sh_ent;

    int tid = threadIdx.x;
    int wid = tid >> 5;
    int lane = tid & 31;
    int blk_tok0 = blockIdx.x * tok_per_blk;
    int tok0w = blk_tok0 + wid * ROWS_W;
    float* wbuf = sx + wid * (STG * WBUF);

    // Start HBM traffic immediately (warp-private buffers: no barrier needed)
    warp_issue(x, wbuf, tok0w, 0, lane, N);
    warp_issue(x, wbuf, tok0w, 1, lane, N);

    // Stage duplicated W (64KB) into shared; single block barrier in kernel
    for (int i = tid; i < E * DDIM; i += TPB) {
        float w = Wg[i];
        ((float2*)sW2)[i] = make_float2(w, w);
    }
    if (tid < E) { sh_psum[tid] = 0.f; sh_cnt[tid] = 0u; }
    if (tid == 0) sh_ent = 0.f;
    __syncthreads();

    int pairIdx = wid * 32 + lane;
    int tokenA = blk_tok0 + 2 * pairIdx;
    int tokenB = tokenA + 1;
    bool validA = (2 * pairIdx < tok_per_blk) && (tokenA < N);
    bool validB = (2 * pairIdx + 1 < tok_per_blk) && (tokenB < N);

    const ulonglong2* __restrict__ w2 = (const ulonglong2*)sW2;
    int swz = lane & 7;

    // Packed accumulators: lo lane = tokenA chain, hi lane = tokenB chain.
    // Each component is a STRICT ascending-d scalar fmaf chain — bit-identical
    // to the passing kernels (top-k index ties depend on it; do not reorder).
    unsigned long long acc2[E];
#pragma unroll
    for (int e = 0; e < E; ++e) acc2[e] = 0ull;

    for (int c = 0; c < NCH; ++c) {
        if (c < NCH - 1) asm volatile("cp.async.wait_group 1;\n" ::: "memory");
        else             asm volatile("cp.async.wait_group 0;\n" ::: "memory");
        __syncwarp();

        const float4* rA = (const float4*)(wbuf + (c % STG) * WBUF + (2 * lane) * CFLOAT);
        const float4* rB = rA + CSLOT;           // next row (+32 floats)
#pragma unroll
        for (int j = 0; j < CSLOT; ++j) {
            float4 a = rA[j ^ swz];
            float4 b = rB[j ^ swz];
            unsigned long long p0 = pack2(a.x, b.x);
            unsigned long long p1 = pack2(a.y, b.y);
            unsigned long long p2 = pack2(a.z, b.z);
            unsigned long long p3 = pack2(a.w, b.w);
            int dbase = c * CFLOAT + j * 4;
#pragma unroll
            for (int e = 0; e < E; ++e) {
                const ulonglong2* wp = w2 + ((e * DDIM + dbase) >> 1); // uniform broadcast
                ulonglong2 w01 = wp[0];
                ulonglong2 w23 = wp[1];
                fma2(acc2[e], p0, w01.x);
                fma2(acc2[e], p1, w01.y);
                fma2(acc2[e], p2, w23.x);
                fma2(acc2[e], p3, w23.y);
            }
        }
        if (c + 2 < NCH) warp_issue(x, wbuf, tok0w, c + 2, lane, N);
    }

    // ---- epilogue: softmax / top-k / stats for both tokens ----
    int kk = *pk; kk = kk < 1 ? 1 : (kk > E ? E : kk);
    float* out_dw  = out;
    float* out_idx = out + (size_t)N * kk;
    float* out_lg  = out + (size_t)2 * N * kk;

    float ent_sum_local = 0.f;
    float psum_local[E];
#pragma unroll
    for (int e = 0; e < E; ++e) psum_local[e] = 0.f;
    unsigned selA = 0u, selB = 0u;

#pragma unroll
    for (int t = 0; t < 2; ++t) {
        bool valid = t == 0 ? validA : validB;
        int token = t == 0 ? tokenA : tokenB;
        float acc[E];
#pragma unroll
        for (int e = 0; e < E; ++e) {
            unsigned long long v = acc2[e];
            acc[e] = t == 0 ? __uint_as_float((unsigned)v)
                            : __uint_as_float((unsigned)(v >> 32));
        }

        if (valid) {
            float4* lp = (float4*)(out_lg + (size_t)token * E);
            lp[0] = make_float4(acc[0], acc[1], acc[2], acc[3]);
            lp[1] = make_float4(acc[4], acc[5], acc[6], acc[7]);
        }

        float m = acc[0];
#pragma unroll
        for (int e = 1; e < E; ++e) m = fmaxf(m, acc[e]);
        float p[E], s = 0.f;
#pragma unroll
        for (int e = 0; e < E; ++e) { p[e] = __expf(acc[e] - m); s += p[e]; }
        float inv = 1.f / s;
        float logs = __logf(s);
        float ent = 0.f;
#pragma unroll
        for (int e = 0; e < E; ++e) ent -= (p[e] * inv) * (acc[e] - m - logs);

        unsigned selmask = 0u;
        float tmp[E];
#pragma unroll
        for (int e = 0; e < E; ++e) tmp[e] = p[e];
#pragma unroll
        for (int r = 0; r < E; ++r) {
            if (r < kk) {
                int bi = 0; float bv = tmp[0];
#pragma unroll
                for (int e = 1; e < E; ++e) { if (tmp[e] > bv) { bv = tmp[e]; bi = e; } }
                if (valid) {
                    out_dw [(size_t)token * kk + r] = bv * inv;
                    out_idx[(size_t)token * kk + r] = (float)bi;
                }
                selmask |= (1u << bi);
#pragma unroll
                for (int e = 0; e < E; ++e) if (e == bi) tmp[e] = -1.f;
            }
        }

        if (valid) {
            ent_sum_local += ent;
#pragma unroll
            for (int e = 0; e < E; ++e) psum_local[e] += p[e] * inv;
            if (t == 0) selA = selmask; else selB = selmask;
        }
    }

    // Warp reduction -> shared atomics -> one global atomic set per block
    float entw = ent_sum_local;
#pragma unroll
    for (int o = 16; o > 0; o >>= 1) entw += __shfl_xor_sync(0xffffffffu, entw, o);
    float psum[E];
#pragma unroll
    for (int e = 0; e < E; ++e) {
        float v = psum_local[e];
#pragma unroll
        for (int o = 16; o > 0; o >>= 1) v += __shfl_xor_sync(0xffffffffu, v, o);
        psum[e] = v;
    }
    bool lane0 = (lane == 0);
    if (lane0) atomicAdd(&sh_ent, entw);
#pragma unroll
    for (int e = 0; e < E; ++e) {
        unsigned ba = __ballot_sync(0xffffffffu, (selA >> e) & 1u);
        unsigned bb = __ballot_sync(0xffffffffu, (selB >> e) & 1u);
        if (lane0) {
            atomicAdd(&sh_cnt[e], (unsigned)(__popc(ba) + __popc(bb)));
            atomicAdd(&sh_psum[e], psum[e]);
        }
    }
    __syncthreads();
    if (tid < E) {
        atomicAdd(&g_cnt[tid], sh_cnt[tid]);
        atomicAdd(&g_prob_sum[tid], sh_psum[tid]);
    }
    if (tid == E) atomicAdd(&g_ent_sum, sh_ent);

    // ---- last-block-done finalize (fused; single launch) ----
    __threadfence();
    __shared__ unsigned sh_last;
    if (tid == 0) sh_last = atomicAdd(&g_done, 1u);
    __syncthreads();
    if (sh_last != gridDim.x - 1u) return;

    if (tid == 0) {
        float* base = out + (size_t)2 * N * kk + (size_t)N * E;
        long long total_cap = (long long)((double)N * (double)kk * 1.25);
        long long per_cap = total_cap / E; if (per_cap < 1) per_cap = 1;
        float invN = 1.f / (float)N;
        float lb = 0.f; int nd = 0;
        for (int e = 0; e < E; ++e) {
            float cnt = (float)g_cnt[e];
            float usage = cnt * invN;
            float avg = g_prob_sum[e] * invN;
            lb += usage * avg;
            if ((long long)g_cnt[e] > per_cap) nd++;
            base[3 + e] = usage;
        }
        base[0] = lb * (float)E;
        float entm = g_ent_sum * invN;
        float rel = logf((float)E) - entm;
        base[1] = rel > 0.f ? rel : 0.f;
        base[2] = (float)nd;

        // Reset accumulators for the next launch / graph replay.
        for (int e = 0; e < E; ++e) { g_cnt[e] = 0u; g_prob_sum[e] = 0.f; }
        g_ent_sum = 0.f;
        g_done = 0u;
    }
}

extern "C" void kernel_launch(void* const* d_in, const int* in_sizes, int n_in,
                              void* d_out, int out_size) {
    const float* x = (const float*)d_in[0];
    const float* W = (const float*)d_in[1];
    const int*  pk = (const int*)d_in[2];
    int N = in_sizes[0] / DDIM;
    float* out = (float*)d_out;

    int grid = GRID;
    int tok_per_blk = (N + grid - 1) / grid;        // 222 for N=32768
    if (tok_per_blk > 2 * TPB) {                     // safety for other shapes
        tok_per_blk = 2 * TPB;
        grid = (N + tok_per_blk - 1) / tok_per_blk;
    }
    cudaFuncSetAttribute(router_main, cudaFuncAttributeMaxDynamicSharedMemorySize, SMEM_BYTES);
    router_main<<<grid, TPB, SMEM_BYTES>>>(x, W, pk, out, N, tok_per_blk);
}